// round 15
// baseline (speedup 1.0000x reference)
#include <cuda_runtime.h>

// Scratch for the extracted diagonal (allocation-free: __device__ global).
__device__ float g_diag[4096];

// Kernel A: pull diag(W) out of the dense [4096,4096] matrix, then signal
// the dependent scale kernel (PDL) so its launch overlaps ours.
__global__ void extract_diag_kernel(const float* __restrict__ W) {
    int j = blockIdx.x * blockDim.x + threadIdx.x;
    if (j < 4096) {
        g_diag[j] = __ldg(&W[(size_t)j * 4097u]);
    }
    __threadfence();
    cudaTriggerProgrammaticLaunchCompletion();
}

// Kernel B: y = x * diag (columnwise), 4 linear streams, ILP=4.
// Total 8,388,608 float4; Q = 2,097,152 (multiple of 1024, the float4 row
// width, so all four elements of a thread share one diag value).
// Stores are write-through (__stwt): y is write-once and never read, so
// skip L2 write allocation entirely — the write stream goes straight to
// DRAM and stops competing with the read stream for LTS lines.
#define Q 2097152u

__global__ void __launch_bounds__(256) diag_scale_kernel(
        const float4* __restrict__ x, float4* __restrict__ y) {
    const unsigned int i = blockIdx.x * blockDim.x + threadIdx.x;  // < Q

    // x-loads are independent of g_diag: issue all four BEFORE the PDL
    // sync so they overlap the extract kernel's tail.
    float4 a = __ldcs(&x[i]);
    float4 b = __ldcs(&x[i + Q]);
    float4 c = __ldcs(&x[i + 2u * Q]);
    float4 e = __ldcs(&x[i + 3u * Q]);

    // Wait for extract's writes, then one diag load serves all 4 streams.
    cudaGridDependencySynchronize();
    const float4* d4 = reinterpret_cast<const float4*>(g_diag);
    const float4 d = __ldg(&d4[i & 1023u]);

    a.x *= d.x; a.y *= d.y; a.z *= d.z; a.w *= d.w;
    b.x *= d.x; b.y *= d.y; b.z *= d.z; b.w *= d.w;
    c.x *= d.x; c.y *= d.y; c.z *= d.z; c.w *= d.w;
    e.x *= d.x; e.y *= d.y; e.z *= d.z; e.w *= d.w;

    __stwt(&y[i], a);
    __stwt(&y[i + Q], b);
    __stwt(&y[i + 2u * Q], c);
    __stwt(&y[i + 3u * Q], e);
}

extern "C" void kernel_launch(void* const* d_in, const int* in_sizes, int n_in,
                              void* d_out, int out_size) {
    const float* x = (const float*)d_in[0];
    const float* W = (const float*)d_in[1];
    float* y = (float*)d_out;

    extract_diag_kernel<<<16, 256>>>(W);

    // Scale kernel with programmatic stream serialization: its launch and
    // pre-sync prologue overlap the extract kernel.
    cudaLaunchConfig_t cfg = {};
    cfg.gridDim = dim3(8192);
    cfg.blockDim = dim3(256);
    cfg.dynamicSmemBytes = 0;
    cfg.stream = 0;
    cudaLaunchAttribute attrs[1];
    attrs[0].id = cudaLaunchAttributeProgrammaticStreamSerialization;
    attrs[0].val.programmaticStreamSerializationAllowed = 1;
    cfg.attrs = attrs;
    cfg.numAttrs = 1;
    cudaLaunchKernelEx(&cfg, diag_scale_kernel, (const float4*)x, (float4*)y);
}

// round 16
// speedup vs baseline: 1.0379x; 1.0379x over previous
#include <cuda_runtime.h>

// Scratch for the extracted diagonal (allocation-free: __device__ global).
__device__ float g_diag[4096];

// Kernel A: pull diag(W) out of the dense [4096,4096] matrix, then signal
// the dependent scale kernel (PDL) so its launch overlaps ours.
__global__ void extract_diag_kernel(const float* __restrict__ W) {
    int j = blockIdx.x * blockDim.x + threadIdx.x;
    if (j < 4096) {
        g_diag[j] = __ldg(&W[(size_t)j * 4097u]);
    }
    __threadfence();
    cudaTriggerProgrammaticLaunchCompletion();
}

// Kernel B: y = x * diag (columnwise), 4 linear streams, ILP=4.
// Total 8,388,608 float4; Q = total/4 = 2,097,152 (multiple of 1024, the
// float4 row width, so all four elements of a thread share one diag value).
//
// Measured-best configuration (45.568us total, kernel 37.3us @ 5.78TB/s):
//  - flat one-shot grid: all 4 x-loads front-batched per thread (max MLP)
//  - .cs streaming hints on the 256MB write-once/read-once traffic
//    (evict-first; write-allocate kept — .wt measured slower)
//  - PDL hides the extract node behind the scale kernel's launch + x-load
//    prologue; grid-dependency sync only before the diag read.
#define Q 2097152u

__global__ void __launch_bounds__(256) diag_scale_kernel(
        const float4* __restrict__ x, float4* __restrict__ y) {
    const unsigned int i = blockIdx.x * blockDim.x + threadIdx.x;  // < Q

    // x-loads are independent of g_diag: issue all four BEFORE the PDL
    // sync so they overlap the extract kernel's tail.
    float4 a = __ldcs(&x[i]);
    float4 b = __ldcs(&x[i + Q]);
    float4 c = __ldcs(&x[i + 2u * Q]);
    float4 e = __ldcs(&x[i + 3u * Q]);

    // Wait for extract's writes, then one diag load serves all 4 streams.
    cudaGridDependencySynchronize();
    const float4* d4 = reinterpret_cast<const float4*>(g_diag);
    const float4 d = __ldg(&d4[i & 1023u]);

    a.x *= d.x; a.y *= d.y; a.z *= d.z; a.w *= d.w;
    b.x *= d.x; b.y *= d.y; b.z *= d.z; b.w *= d.w;
    c.x *= d.x; c.y *= d.y; c.z *= d.z; c.w *= d.w;
    e.x *= d.x; e.y *= d.y; e.z *= d.z; e.w *= d.w;

    __stcs(&y[i], a);
    __stcs(&y[i + Q], b);
    __stcs(&y[i + 2u * Q], c);
    __stcs(&y[i + 3u * Q], e);
}

extern "C" void kernel_launch(void* const* d_in, const int* in_sizes, int n_in,
                              void* d_out, int out_size) {
    const float* x = (const float*)d_in[0];
    const float* W = (const float*)d_in[1];
    float* y = (float*)d_out;

    extract_diag_kernel<<<16, 256>>>(W);

    // Scale kernel with programmatic stream serialization: its launch and
    // pre-sync prologue overlap the extract kernel.
    cudaLaunchConfig_t cfg = {};
    cfg.gridDim = dim3(8192);
    cfg.blockDim = dim3(256);
    cfg.dynamicSmemBytes = 0;
    cfg.stream = 0;
    cudaLaunchAttribute attrs[1];
    attrs[0].id = cudaLaunchAttributeProgrammaticStreamSerialization;
    attrs[0].val.programmaticStreamSerializationAllowed = 1;
    cfg.attrs = attrs;
    cfg.numAttrs = 1;
    cudaLaunchKernelEx(&cfg, diag_scale_kernel, (const float4*)x, (float4*)y);
}